// round 7
// baseline (speedup 1.0000x reference)
#include <cuda_runtime.h>
#include <cuda_fp16.h>
#include <math.h>
#include <stdint.h>

#define Nn 4096
#define NHEADS 8
#define SCALE 0.125f
#define FULLM 0xffffffffu

// fp16 projections
__device__ __half g_K1H[Nn * 512];
__device__ __half g_K2H[Nn * 512];
__device__ __half g_V1H[Nn * 512];
__device__ __half g_V2H[Nn * 512];
// fp32 attention outputs (atomic accumulation, unnormalized)
__device__ float g_O1f[Nn * 512];
__device__ float g_O2f[Nn * 512];
__device__ float g_rsum[NHEADS * Nn];
__device__ float g_csum[NHEADS * Nn];

struct Ptrs {
    const float* p[16];
};

__device__ __forceinline__ void mma_f16(float c[4],
                                        uint32_t a0, uint32_t a1, uint32_t a2, uint32_t a3,
                                        uint32_t b0, uint32_t b1) {
    asm volatile(
        "mma.sync.aligned.m16n8k16.row.col.f32.f16.f16.f32 "
        "{%0,%1,%2,%3}, {%4,%5,%6,%7}, {%8,%9}, {%0,%1,%2,%3};\n"
        : "+f"(c[0]), "+f"(c[1]), "+f"(c[2]), "+f"(c[3])
        : "r"(a0), "r"(a1), "r"(a2), "r"(a3), "r"(b0), "r"(b1));
}

__device__ __forceinline__ void ldm_x4(uint32_t r[4], const void* ptr) {
    uint32_t addr = (uint32_t)__cvta_generic_to_shared(ptr);
    asm volatile("ldmatrix.sync.aligned.m8n8.x4.shared.b16 {%0,%1,%2,%3}, [%4];"
                 : "=r"(r[0]), "=r"(r[1]), "=r"(r[2]), "=r"(r[3]) : "r"(addr));
}

__device__ __forceinline__ void ldm_x4_trans(uint32_t r[4], const void* ptr) {
    uint32_t addr = (uint32_t)__cvta_generic_to_shared(ptr);
    asm volatile("ldmatrix.sync.aligned.m8n8.x4.trans.shared.b16 {%0,%1,%2,%3}, [%4];"
                 : "=r"(r[0]), "=r"(r[1]), "=r"(r[2]), "=r"(r[3]) : "r"(addr));
}

__device__ __forceinline__ void cp16(void* smem_dst, const void* gsrc) {
    uint32_t d = (uint32_t)__cvta_generic_to_shared(smem_dst);
    asm volatile("cp.async.cg.shared.global [%0], [%1], 16;" :: "r"(d), "l"(gsrc));
}

__device__ __forceinline__ uint4 pack8h(float4 v0, float4 v1) {
    uint4 u;
    __half2* h = (__half2*)&u;
    h[0] = __floats2half2_rn(v0.x, v0.y);
    h[1] = __floats2half2_rn(v0.z, v0.w);
    h[2] = __floats2half2_rn(v1.x, v1.y);
    h[3] = __floats2half2_rn(v1.z, v1.w);
    return u;
}

// ---------------------------------------------------------------------------
// zero accumulators: O1f (524288 f4), O2f (524288 f4), rsum (8192 f4), csum (8192 f4)
// grid 4160 x 256
// ---------------------------------------------------------------------------
__global__ void zero_kernel() {
    int i = blockIdx.x * 256 + threadIdx.x;
    float4 z = make_float4(0.f, 0.f, 0.f, 0.f);
    if (i < 524288)       ((float4*)g_O1f)[i] = z;
    else if (i < 1048576) ((float4*)g_O2f)[i - 524288] = z;
    else if (i < 1056768) ((float4*)g_rsum)[i - 1048576] = z;
    else                  ((float4*)g_csum)[i - 1056768] = z;
}

__global__ void recip_kernel() {
    int i = blockIdx.x * 256 + threadIdx.x;   // 32768 total
    g_rsum[i] = 1.0f / g_rsum[i];
    g_csum[i] = 1.0f / g_csum[i];
}

// ---------------------------------------------------------------------------
// Projection (fp16 mma): C[4096,512] = A[4096,256] @ W[256,512] + bias -> fp16
// grid (8, 32, 4), 256 thr.
// ---------------------------------------------------------------------------
__global__ __launch_bounds__(256) void proj_f16_kernel(Ptrs in) {
    const float *A, *W, *bias;
    __half* C;
    switch (blockIdx.z) {
        case 0: A = in.p[0]; W = in.p[4];  bias = in.p[5];  C = g_K1H; break;
        case 1: A = in.p[1]; W = in.p[6];  bias = in.p[7];  C = g_V1H; break;
        case 2: A = in.p[2]; W = in.p[8];  bias = in.p[9];  C = g_K2H; break;
        default:A = in.p[3]; W = in.p[10]; bias = in.p[11]; C = g_V2H; break;
    }
    __shared__ __half As[128 * 72];
    __shared__ __half Ws[64 * 72];

    const int tid = threadIdx.x;
    const int lane = tid & 31, wid = tid >> 5;
    const int q = lane & 3, g = lane >> 2;
    const int row0 = blockIdx.y * 128;
    const int col0 = blockIdx.x * 64;
    const int brow = ((lane >> 3) & 1) * 8 + (lane & 7);
    const int bcoff = (lane >> 4) * 8;
    const int arow = wid * 16 + (lane & 7) + ((lane >> 3) & 1) * 8;
    const int acoff = (lane >> 4) * 8;

    float o[8][4];
#pragma unroll
    for (int nt = 0; nt < 8; nt++)
#pragma unroll
        for (int j = 0; j < 4; j++) o[nt][j] = 0.f;

    for (int k0 = 0; k0 < 256; k0 += 64) {
        __syncthreads();
#pragma unroll
        for (int it = 0; it < 4; it++) {
            int j = tid + it * 256;
            int rr = j >> 3, c8 = j & 7;
            const float* src = &A[(row0 + rr) * 256 + k0 + c8 * 8];
            *(uint4*)&As[rr * 72 + c8 * 8] =
                pack8h(*(const float4*)src, *(const float4*)(src + 4));
        }
#pragma unroll
        for (int it = 0; it < 2; it++) {
            int j = tid + it * 256;
            int rr = j >> 3, c8 = j & 7;
            const float* src = &W[(k0 + rr) * 512 + col0 + c8 * 8];
            *(uint4*)&Ws[rr * 72 + c8 * 8] =
                pack8h(*(const float4*)src, *(const float4*)(src + 4));
        }
        __syncthreads();
#pragma unroll
        for (int kk = 0; kk < 4; kk++) {
            uint32_t a[4];
            ldm_x4(a, As + arow * 72 + kk * 16 + acoff);
#pragma unroll
            for (int dtp = 0; dtp < 4; dtp++) {
                uint32_t b[4];
                ldm_x4_trans(b, Ws + (kk * 16 + brow) * 72 + dtp * 16 + bcoff);
                mma_f16(o[2 * dtp],     a[0], a[1], a[2], a[3], b[0], b[1]);
                mma_f16(o[2 * dtp + 1], a[0], a[1], a[2], a[3], b[2], b[3]);
            }
        }
    }

    const int r = row0 + wid * 16 + g;
#pragma unroll
    for (int nt = 0; nt < 8; nt++) {
        int c = col0 + nt * 8 + 2 * q;
        float b0 = bias[c], b1 = bias[c + 1];
        __half2 h0 = __floats2half2_rn(o[nt][0] + b0, o[nt][1] + b1);
        __half2 h1 = __floats2half2_rn(o[nt][2] + b0, o[nt][3] + b1);
        *(uint32_t*)&C[r * 512 + c] = *(uint32_t*)&h0;
        *(uint32_t*)&C[(r + 8) * 512 + c] = *(uint32_t*)&h1;
    }
}

// ---------------------------------------------------------------------------
// Fused attention: S = K1 K2^T (fp16 mma) -> P = exp(S*scale) (smem only) ->
//   o2[n] += P @ V2  (register accum, REDG at end)
//   o1[m] += P^T @ V1 (REDG per tile)
//   rsum (register accum + REDG), csum (REDG per tile)
// grid (32 n-blocks, 8 heads, 4 m-quarters), 256 thr, ~124KB smem.
// ---------------------------------------------------------------------------
#define NITER 8

__global__ __launch_bounds__(256) void fused_attn_kernel() {
    extern __shared__ __half sm[];
    __half* Ps  = sm;                    // [128][136], aliases K1 tmp at init
    __half* V1s = sm + 17408;            // [128][72]
    __half* K2s = sm + 26624;            // 2 x [128][72]
    __half* V2s = sm + 45056;            // 2 x [128][72]
    uint32_t* PsU = (uint32_t*)sm;       // uint32 view, stride 68

    const int n0 = blockIdx.x * 128;
    const int head = blockIdx.y;
    const int hc = head * 64;
    const int mq = blockIdx.z;
    const int tid = threadIdx.x;
    const int lane = tid & 31, wid = tid >> 5;
    const int q = lane & 3, g = lane >> 2;
    // S-phase warp layout: (wn 0..3) rows, (wm 0..1) cols
    const int wn = wid >> 1, wm = wid & 1;
    const int rbase = wn * 32;
    const int cbase = wm * 64;

    // ---- init: load K1 (into Ps region) and V1 ----
#pragma unroll
    for (int it = 0; it < 4; it++) {
        int j = tid + it * 256;
        int rr = j >> 3, c8 = j & 7;
        cp16(Ps + rr * 72 + c8 * 8,  g_K1H + (n0 + rr) * 512 + hc + c8 * 8);
        cp16(V1s + rr * 72 + c8 * 8, g_V1H + (n0 + rr) * 512 + hc + c8 * 8);
    }
    asm volatile("cp.async.commit_group;" ::: "memory");
    asm volatile("cp.async.wait_group 0;" ::: "memory");
    __syncthreads();

    // K1 A-fragments (2 stripes x 4 ksteps)
    uint32_t af[2][4][4];
    {
        const int arow_lm0 = rbase + (lane & 7) + ((lane >> 3) & 1) * 8;
        const int acoff = (lane >> 4) * 8;
#pragma unroll
        for (int mt = 0; mt < 2; mt++)
#pragma unroll
            for (int kk = 0; kk < 4; kk++)
                ldm_x4(af[mt][kk], Ps + (arow_lm0 + mt * 16) * 72 + kk * 16 + acoff);
    }
    __syncthreads();   // K1 tmp free; Ps can be overwritten

    auto issue = [&](int i, int buf) {
        const int m0 = (mq * NITER + i) * 128;
        __half* Kd = K2s + buf * 9216;
        __half* Vd = V2s + buf * 9216;
#pragma unroll
        for (int it = 0; it < 4; it++) {
            int j = tid + it * 256;
            int rr = j >> 3, c8 = j & 7;
            cp16(Kd + rr * 72 + c8 * 8, g_K2H + (m0 + rr) * 512 + hc + c8 * 8);
            cp16(Vd + rr * 72 + c8 * 8, g_V2H + (m0 + rr) * 512 + hc + c8 * 8);
        }
        asm volatile("cp.async.commit_group;" ::: "memory");
    };

    issue(0, 0);
    issue(1, 1);

    float o2a[8][4];
#pragma unroll
    for (int dt = 0; dt < 8; dt++)
#pragma unroll
        for (int j = 0; j < 4; j++) o2a[dt][j] = 0.f;
    float rloc[2][2] = {{0.f, 0.f}, {0.f, 0.f}};

    // phase-2 lane constants
    const int brow = ((lane >> 3) & 1) * 8 + (lane & 7);
    const int bcoff = (lane >> 4) * 8;
    const int arow2 = wid * 16 + (lane & 7) + ((lane >> 3) & 1) * 8;  // o2 A rows
    const int acoff2 = (lane >> 4) * 8;
    const int krowoff = (lane & 7) + ((lane >> 4) & 1) * 8;           // o1 A (trans)
    const int mcoloff = wid * 16 + ((lane >> 3) & 1) * 8;

    for (int i = 0; i < NITER; i++) {
        if (i == NITER - 1) asm volatile("cp.async.wait_group 0;" ::: "memory");
        else                asm volatile("cp.async.wait_group 1;" ::: "memory");
        __syncthreads();

        const int buf = i & 1;
        const __half* K2c = K2s + buf * 9216;
        const __half* V2c = V2s + buf * 9216;
        const int m0 = (mq * NITER + i) * 128;

        // ---- S tile + exp -> Ps; rsum local accum; csum REDG ----
        float cps[8][2];
#pragma unroll
        for (int nt = 0; nt < 8; nt++) { cps[nt][0] = 0.f; cps[nt][1] = 0.f; }

#pragma unroll
        for (int mt = 0; mt < 2; mt++) {
            const int arow = rbase + mt * 16 + g;
            float rp0 = 0.f, rp1 = 0.f;
#pragma unroll
            for (int nt = 0; nt < 8; nt++) {
                float s[4] = {0.f, 0.f, 0.f, 0.f};
                const int browx = cbase + nt * 8 + g;
#pragma unroll
                for (int kk = 0; kk < 4; kk++) {
                    const uint32_t* bp = (const uint32_t*)(K2c + browx * 72 + kk * 16);
                    mma_f16(s, af[mt][kk][0], af[mt][kk][1], af[mt][kk][2], af[mt][kk][3],
                            bp[q], bp[q + 4]);
                }
                float p0 = __expf(s[0] * SCALE);
                float p1 = __expf(s[1] * SCALE);
                float p2 = __expf(s[2] * SCALE);
                float p3 = __expf(s[3] * SCALE);
                rp0 += p0 + p1; rp1 += p2 + p3;
                cps[nt][0] += p0 + p2; cps[nt][1] += p1 + p3;
                __half2 h0 = __floats2half2_rn(p0, p1);
                __half2 h1 = __floats2half2_rn(p2, p3);
                int ucol = cbase / 2 + nt * 4 + q;
                PsU[arow * 68 + ucol] = *(uint32_t*)&h0;
                PsU[(arow + 8) * 68 + ucol] = *(uint32_t*)&h1;
            }
            rloc[mt][0] += rp0;
            rloc[mt][1] += rp1;
        }
        // csum for this m-block (reduce over g lanes, REDG)
#pragma unroll
        for (int nt = 0; nt < 8; nt++) {
            float v0 = cps[nt][0], v1 = cps[nt][1];
            v0 += __shfl_xor_sync(FULLM, v0, 4);
            v0 += __shfl_xor_sync(FULLM, v0, 8);
            v0 += __shfl_xor_sync(FULLM, v0, 16);
            v1 += __shfl_xor_sync(FULLM, v1, 4);
            v1 += __shfl_xor_sync(FULLM, v1, 8);
            v1 += __shfl_xor_sync(FULLM, v1, 16);
            if (lane < 4) {
                atomicAdd(&g_csum[head * Nn + m0 + cbase + nt * 8 + 2 * q], v0);
                atomicAdd(&g_csum[head * Nn + m0 + cbase + nt * 8 + 2 * q + 1], v1);
            }
        }
        __syncthreads();   // Ps complete

        // ---- o2 += Ps @ V2  (warp rows wid*16, 64 d-cols, K=128) ----
#pragma unroll
        for (int kc = 0; kc < 8; kc++) {
            uint32_t a[4];
            ldm_x4(a, Ps + arow2 * 136 + kc * 16 + acoff2);
#pragma unroll
            for (int dtp = 0; dtp < 4; dtp++) {
                uint32_t b[4];
                ldm_x4_trans(b, V2c + (kc * 16 + brow) * 72 + dtp * 16 + bcoff);
                mma_f16(o2a[2 * dtp],     a[0], a[1], a[2], a[3], b[0], b[1]);
                mma_f16(o2a[2 * dtp + 1], a[0], a[1], a[2], a[3], b[2], b[3]);
            }
        }

        // ---- o1[m] = Ps^T @ V1 -> REDG ----
        {
            float o1c[8][4];
#pragma unroll
            for (int dt = 0; dt < 8; dt++)
#pragma unroll
                for (int j = 0; j < 4; j++) o1c[dt][j] = 0.f;
#pragma unroll
            for (int kc = 0; kc < 8; kc++) {
                uint32_t a[4];
                ldm_x4_trans(a, Ps + (kc * 16 + krowoff) * 136 + mcoloff);
#pragma unroll
                for (int dtp = 0; dtp < 4; dtp++) {
                    uint32_t b[4];
                    ldm_x4_trans(b, V1s + (kc * 16 + brow) * 72 + dtp * 16 + bcoff);
                    mma_f16(o1c[2 * dtp],     a[0], a[1], a[2], a[3], b[0], b[1]);
                    mma_f16(o1c[2 * dtp + 1], a[0], a[1], a[2], a[3], b[2], b[3]);
                }
            }
            const int rM = m0 + wid * 16 + g;
            float* O1p = g_O1f + rM * 512 + hc;
#pragma unroll
            for (int dt = 0; dt < 8; dt++) {
                atomicAdd(&O1p[dt * 8 + 2 * q], o1c[dt][0]);
                atomicAdd(&O1p[dt * 8 + 2 * q + 1], o1c[dt][1]);
                atomicAdd(&O1p[8 * 512 + dt * 8 + 2 * q], o1c[dt][2]);
                atomicAdd(&O1p[8 * 512 + dt * 8 + 2 * q + 1], o1c[dt][3]);
            }
        }
        __syncthreads();   // Ps/V2 reads done before next overwrite
        if (i + 2 < NITER) issue(i + 2, buf);
    }

    // ---- flush o2 and rsum ----
    {
        const int rN = n0 + wid * 16 + g;
        float* O2p = g_O2f + rN * 512 + hc;
#pragma unroll
        for (int dt = 0; dt < 8; dt++) {
            atomicAdd(&O2p[dt * 8 + 2 * q], o2a[dt][0]);
            atomicAdd(&O2p[dt * 8 + 2 * q + 1], o2a[dt][1]);
            atomicAdd(&O2p[8 * 512 + dt * 8 + 2 * q], o2a[dt][2]);
            atomicAdd(&O2p[8 * 512 + dt * 8 + 2 * q + 1], o2a[dt][3]);
        }
    }
#pragma unroll
    for (int mt = 0; mt < 2; mt++) {
        float rp0 = rloc[mt][0], rp1 = rloc[mt][1];
        rp0 += __shfl_xor_sync(FULLM, rp0, 1);
        rp0 += __shfl_xor_sync(FULLM, rp0, 2);
        rp1 += __shfl_xor_sync(FULLM, rp1, 1);
        rp1 += __shfl_xor_sync(FULLM, rp1, 2);
        if (q == 0) {
            const int arow = rbase + mt * 16 + g;
            atomicAdd(&g_rsum[head * Nn + n0 + arow], rp0);
            atomicAdd(&g_rsum[head * Nn + n0 + arow + 8], rp1);
        }
    }
}

// ---------------------------------------------------------------------------
// Output GEMM (fp16 mma): out = (Of * inv) @ Wo + bias
// grid (4, 32, 2): z=0 -> o1 (csum-inv, wo1), z=1 -> o2 (rsum-inv, wo2)
// ---------------------------------------------------------------------------
__global__ __launch_bounds__(256) void outproj_f16_kernel(Ptrs in, float* out) {
    const float *Of, *inv, *W, *bias;
    float* C;
    if (blockIdx.z == 0) {
        Of = g_O1f; inv = g_csum;
        W = in.p[12]; bias = in.p[13]; C = out;
    } else {
        Of = g_O2f; inv = g_rsum;
        W = in.p[14]; bias = in.p[15]; C = out + Nn * 256;
    }
    __shared__ __half As[128 * 72];
    __shared__ __half Ws[64 * 72];

    const int tid = threadIdx.x;
    const int lane = tid & 31, wid = tid >> 5;
    const int q = lane & 3, g = lane >> 2;
    const int row0 = blockIdx.y * 128;
    const int col0 = blockIdx.x * 64;
    const int brow = ((lane >> 3) & 1) * 8 + (lane & 7);
    const int bcoff = (lane >> 4) * 8;
    const int arow = wid * 16 + (lane & 7) + ((lane >> 3) & 1) * 8;
    const int acoff = (lane >> 4) * 8;

    float o[8][4];
#pragma unroll
    for (int nt = 0; nt < 8; nt++)
#pragma unroll
        for (int j = 0; j < 4; j++) o[nt][j] = 0.f;

    for (int k0 = 0; k0 < 512; k0 += 64) {
        const int head = k0 >> 6;
        __syncthreads();
        // A staging: normalize fp32 partials -> fp16
#pragma unroll
        for (int it = 0; it < 4; it++) {
            int j = tid + it * 256;
            int rr = j >> 3, c8 = j & 7;
            const float* src = &Of[(size_t)(row0 + rr) * 512 + k0 + c8 * 8];
            float iv = inv[head * Nn + row0 + rr];
            float4 f0 = *(const float4*)src;
            float4 f1 = *(const float4*)(src + 4);
            f0.x *= iv; f0.y *= iv; f0.z *= iv; f0.w *= iv;
            f1.x *= iv; f1.y *= iv; f1.z *= iv; f1.w *= iv;
            *(uint4*)&As[rr * 72 + c8 * 8] = pack8h(f0, f1);
        }
#pragma unroll
        for (int it = 0; it < 2; it++) {
            int j = tid + it * 256;
            int rr = j >> 3, c8 = j & 7;
            const float* src = &W[(k0 + rr) * 256 + col0 + c8 * 8];
            *(uint4*)&Ws[rr * 72 + c8 * 8] =
                pack8h(*(const float4*)src, *(const float4*)(src + 4));
        }
        __syncthreads();
#pragma unroll
        for (int kk = 0; kk < 4; kk++) {
            uint32_t a[4];
            ldm_x4(a, As + arow * 72 + kk * 16 + acoff);
#pragma unroll
            for (int dtp = 0; dtp < 4; dtp++) {
                uint32_t b[4];
                ldm_x4_trans(b, Ws + (kk * 16 + brow) * 72 + dtp * 16 + bcoff);
                mma_f16(o[2 * dtp],     a[0], a[1], a[2], a[3], b[0], b[1]);
                mma_f16(o[2 * dtp + 1], a[0], a[1], a[2], a[3], b[2], b[3]);
            }
        }
    }

    const int r = row0 + wid * 16 + g;
#pragma unroll
    for (int nt = 0; nt < 8; nt++) {
        int c = col0 + nt * 8 + 2 * q;
        float b0 = bias[c], b1 = bias[c + 1];
        *(float2*)&C[r * 256 + c] = make_float2(o[nt][0] + b0, o[nt][1] + b1);
        *(float2*)&C[(r + 8) * 256 + c] = make_float2(o[nt][2] + b0, o[nt][3] + b1);
    }
}

extern "C" void kernel_launch(void* const* d_in, const int* in_sizes, int n_in,
                              void* d_out, int out_size) {
    Ptrs ptrs;
    for (int i = 0; i < 16; i++) ptrs.p[i] = (const float*)d_in[i];
    float* out = (float*)d_out;

    const int fused_smem = 63488 * 2;   // 124 KB
    cudaFuncSetAttribute(fused_attn_kernel, cudaFuncAttributeMaxDynamicSharedMemorySize,
                         fused_smem);

    zero_kernel<<<4160, 256>>>();
    {
        dim3 grid(512 / 64, Nn / 128, 4);
        proj_f16_kernel<<<grid, 256>>>(ptrs);
    }
    {
        dim3 grid(Nn / 128, NHEADS, 4);
        fused_attn_kernel<<<grid, 256, fused_smem>>>();
    }
    recip_kernel<<<128, 256>>>();
    {
        dim3 grid(256 / 64, Nn / 128, 2);
        outproj_f16_kernel<<<grid, 256>>>(ptrs, out);
    }
}

// round 8
// speedup vs baseline: 1.2190x; 1.2190x over previous
#include <cuda_runtime.h>
#include <cuda_fp16.h>
#include <math.h>
#include <stdint.h>

#define Nn 4096
#define NHEADS 8
#define FC 0.18033688011112042f   // SCALE * log2(e)
#define FULLM 0xffffffffu

// fp16 projections
__device__ __half g_K1H[Nn * 512];
__device__ __half g_K2H[Nn * 512];
__device__ __half g_V1H[Nn * 512];
__device__ __half g_V2H[Nn * 512];
// fp32 partial attention outputs: slab z = dir*2 + ks (direct stores, no atomics)
__device__ float g_Opf[4][Nn * 512];
__device__ float g_rsum[NHEADS * Nn];
__device__ float g_csum[NHEADS * Nn];

struct Ptrs {
    const float* p[16];
};

__device__ __forceinline__ void mma_f16(float c[4],
                                        uint32_t a0, uint32_t a1, uint32_t a2, uint32_t a3,
                                        uint32_t b0, uint32_t b1) {
    asm volatile(
        "mma.sync.aligned.m16n8k16.row.col.f32.f16.f16.f32 "
        "{%0,%1,%2,%3}, {%4,%5,%6,%7}, {%8,%9}, {%0,%1,%2,%3};\n"
        : "+f"(c[0]), "+f"(c[1]), "+f"(c[2]), "+f"(c[3])
        : "r"(a0), "r"(a1), "r"(a2), "r"(a3), "r"(b0), "r"(b1));
}

__device__ __forceinline__ void ldm_x4(uint32_t r[4], const void* ptr) {
    uint32_t addr = (uint32_t)__cvta_generic_to_shared(ptr);
    asm volatile("ldmatrix.sync.aligned.m8n8.x4.shared.b16 {%0,%1,%2,%3}, [%4];"
                 : "=r"(r[0]), "=r"(r[1]), "=r"(r[2]), "=r"(r[3]) : "r"(addr));
}

__device__ __forceinline__ void ldm_x4_trans(uint32_t r[4], const void* ptr) {
    uint32_t addr = (uint32_t)__cvta_generic_to_shared(ptr);
    asm volatile("ldmatrix.sync.aligned.m8n8.x4.trans.shared.b16 {%0,%1,%2,%3}, [%4];"
                 : "=r"(r[0]), "=r"(r[1]), "=r"(r[2]), "=r"(r[3]) : "r"(addr));
}

__device__ __forceinline__ void cp16(void* smem_dst, const void* gsrc) {
    uint32_t d = (uint32_t)__cvta_generic_to_shared(smem_dst);
    asm volatile("cp.async.cg.shared.global [%0], [%1], 16;" :: "r"(d), "l"(gsrc));
}

__device__ __forceinline__ uint32_t ex2_f16x2(float a, float b) {
    __half2 h = __floats2half2_rn(a, b);
    uint32_t r;
    asm("ex2.approx.f16x2 %0, %1;" : "=r"(r) : "r"(*(uint32_t*)&h));
    return r;
}

__device__ __forceinline__ uint4 pack8h(float4 v0, float4 v1) {
    uint4 u;
    __half2* h = (__half2*)&u;
    h[0] = __floats2half2_rn(v0.x, v0.y);
    h[1] = __floats2half2_rn(v0.z, v0.w);
    h[2] = __floats2half2_rn(v1.x, v1.y);
    h[3] = __floats2half2_rn(v1.z, v1.w);
    return u;
}

// ---------------------------------------------------------------------------
// zero rsum/csum (16384 float4 total) — grid 64 x 256
// ---------------------------------------------------------------------------
__global__ void zero_kernel() {
    int i = blockIdx.x * 256 + threadIdx.x;
    float4 z = make_float4(0.f, 0.f, 0.f, 0.f);
    if (i < 8192) ((float4*)g_rsum)[i] = z;
    else          ((float4*)g_csum)[i - 8192] = z;
}

__global__ void recip_kernel() {
    int i = blockIdx.x * 256 + threadIdx.x;   // 32768 total
    g_rsum[i] = 1.0f / g_rsum[i];
    g_csum[i] = 1.0f / g_csum[i];
}

// ---------------------------------------------------------------------------
// Projection (fp16 mma): C[4096,512] = A[4096,256] @ W[256,512] + bias -> fp16
// grid (8, 32, 4), 256 thr.
// ---------------------------------------------------------------------------
__global__ __launch_bounds__(256) void proj_f16_kernel(Ptrs in) {
    const float *A, *W, *bias;
    __half* C;
    switch (blockIdx.z) {
        case 0: A = in.p[0]; W = in.p[4];  bias = in.p[5];  C = g_K1H; break;
        case 1: A = in.p[1]; W = in.p[6];  bias = in.p[7];  C = g_V1H; break;
        case 2: A = in.p[2]; W = in.p[8];  bias = in.p[9];  C = g_K2H; break;
        default:A = in.p[3]; W = in.p[10]; bias = in.p[11]; C = g_V2H; break;
    }
    __shared__ __half As[128 * 72];
    __shared__ __half Ws[64 * 72];

    const int tid = threadIdx.x;
    const int lane = tid & 31, wid = tid >> 5;
    const int q = lane & 3, g = lane >> 2;
    const int row0 = blockIdx.y * 128;
    const int col0 = blockIdx.x * 64;
    const int brow = ((lane >> 3) & 1) * 8 + (lane & 7);
    const int bcoff = (lane >> 4) * 8;
    const int arow = wid * 16 + (lane & 7) + ((lane >> 3) & 1) * 8;
    const int acoff = (lane >> 4) * 8;

    float o[8][4];
#pragma unroll
    for (int nt = 0; nt < 8; nt++)
#pragma unroll
        for (int j = 0; j < 4; j++) o[nt][j] = 0.f;

    for (int k0 = 0; k0 < 256; k0 += 64) {
        __syncthreads();
#pragma unroll
        for (int it = 0; it < 4; it++) {
            int j = tid + it * 256;
            int rr = j >> 3, c8 = j & 7;
            const float* src = &A[(row0 + rr) * 256 + k0 + c8 * 8];
            *(uint4*)&As[rr * 72 + c8 * 8] =
                pack8h(*(const float4*)src, *(const float4*)(src + 4));
        }
#pragma unroll
        for (int it = 0; it < 2; it++) {
            int j = tid + it * 256;
            int rr = j >> 3, c8 = j & 7;
            const float* src = &W[(k0 + rr) * 512 + col0 + c8 * 8];
            *(uint4*)&Ws[rr * 72 + c8 * 8] =
                pack8h(*(const float4*)src, *(const float4*)(src + 4));
        }
        __syncthreads();
#pragma unroll
        for (int kk = 0; kk < 4; kk++) {
            uint32_t a[4];
            ldm_x4(a, As + arow * 72 + kk * 16 + acoff);
#pragma unroll
            for (int dtp = 0; dtp < 4; dtp++) {
                uint32_t b[4];
                ldm_x4_trans(b, Ws + (kk * 16 + brow) * 72 + dtp * 16 + bcoff);
                mma_f16(o[2 * dtp],     a[0], a[1], a[2], a[3], b[0], b[1]);
                mma_f16(o[2 * dtp + 1], a[0], a[1], a[2], a[3], b[2], b[3]);
            }
        }
    }

    const int r = row0 + wid * 16 + g;
#pragma unroll
    for (int nt = 0; nt < 8; nt++) {
        int c = col0 + nt * 8 + 2 * q;
        float b0 = bias[c], b1 = bias[c + 1];
        __half2 h0 = __floats2half2_rn(o[nt][0] + b0, o[nt][1] + b1);
        __half2 h1 = __floats2half2_rn(o[nt][2] + b0, o[nt][3] + b1);
        *(uint32_t*)&C[r * 512 + c] = *(uint32_t*)&h0;
        *(uint32_t*)&C[(r + 8) * 512 + c] = *(uint32_t*)&h1;
    }
}

// ---------------------------------------------------------------------------
// Fused dual attention, one direction per CTA (operand swap, no transposes):
//   dir=0: Q=K1,K=K2,V=V2 -> o2 rows, rsum     dir=1: Q=K2,K=K1,V=V1 -> o1, csum
// CTA owns 128 output rows x k-half (2048 keys in 32 tiles of 64).
// S tile 128x64 fp16 mma -> ex2.f16x2 -> Ps smem -> o += Ps @ V (registers).
// Partial o direct-stored to g_Opf[z]; row sums via 2-way atomicAdd.
// grid (32, 8, 4), 256 thr, 54KB smem, occ 2.
// ---------------------------------------------------------------------------
__global__ __launch_bounds__(256, 2) void fused_dir_kernel() {
    extern __shared__ __half sm[];
    __half* Ps = sm;                 // [128][72]; also Q staging at init
    __half* Kb = sm + 9216;          // 2 x [64][72]
    __half* Vb = sm + 18432;         // 2 x [64][72]
    uint32_t* PsU = (uint32_t*)sm;   // stride 36 words

    const int n0 = blockIdx.x * 128;
    const int head = blockIdx.y;
    const int hc = head * 64;
    const int z = blockIdx.z;
    const int dir = z >> 1;
    const int ks = z & 1;

    const __half* Qg = dir ? g_K2H : g_K1H;
    const __half* Kg = dir ? g_K1H : g_K2H;
    const __half* Vg = dir ? g_V1H : g_V2H;
    float* sumg = dir ? g_csum : g_rsum;

    const int tid = threadIdx.x;
    const int lane = tid & 31, wid = tid >> 5;
    const int q = lane & 3, g = lane >> 2;
    const int arow_lm = wid * 16 + (lane & 7) + ((lane >> 3) & 1) * 8;
    const int acoff = (lane >> 4) * 8;
    const int brow2 = ((lane >> 3) & 1) * 8 + (lane & 7);
    const int bcoff = (lane >> 4) * 8;
    const int arow = wid * 16 + g;

    // ---- stage Q, build A-fragments ----
#pragma unroll
    for (int it = 0; it < 4; it++) {
        int j = tid + it * 256;
        int rr = j >> 3, c8 = j & 7;
        cp16(Ps + rr * 72 + c8 * 8, Qg + (n0 + rr) * 512 + hc + c8 * 8);
    }
    asm volatile("cp.async.commit_group;" ::: "memory");
    asm volatile("cp.async.wait_group 0;" ::: "memory");
    __syncthreads();

    uint32_t af[4][4];
#pragma unroll
    for (int kk = 0; kk < 4; kk++)
        ldm_x4(af[kk], Ps + arow_lm * 72 + kk * 16 + acoff);
    __syncthreads();   // Ps free

    auto issue = [&](int i, int buf) {
        const int m0 = (ks * 32 + i) * 64;
        __half* Kd = Kb + buf * 4608;
        __half* Vd = Vb + buf * 4608;
#pragma unroll
        for (int it = 0; it < 2; it++) {
            int j = tid + it * 256;
            int rr = j >> 3, c8 = j & 7;
            cp16(Kd + rr * 72 + c8 * 8, Kg + (m0 + rr) * 512 + hc + c8 * 8);
            cp16(Vd + rr * 72 + c8 * 8, Vg + (m0 + rr) * 512 + hc + c8 * 8);
        }
        asm volatile("cp.async.commit_group;" ::: "memory");
    };

    issue(0, 0);
    issue(1, 1);

    float o[8][4];
#pragma unroll
    for (int dt = 0; dt < 8; dt++)
#pragma unroll
        for (int j = 0; j < 4; j++) o[dt][j] = 0.f;
    float rloc0 = 0.f, rloc1 = 0.f;

    for (int i = 0; i < 32; i++) {
        if (i == 31) asm volatile("cp.async.wait_group 0;" ::: "memory");
        else         asm volatile("cp.async.wait_group 1;" ::: "memory");
        __syncthreads();

        const int buf = i & 1;
        const __half* Kc = Kb + buf * 4608;
        const __half* Vc = Vb + buf * 4608;

        // ---- S (warp: 16 rows x 64 cols) + exp -> Ps ----
        float rp0 = 0.f, rp1 = 0.f;
#pragma unroll
        for (int nt = 0; nt < 8; nt++) {
            float s[4] = {0.f, 0.f, 0.f, 0.f};
            const int browx = nt * 8 + g;
#pragma unroll
            for (int kk = 0; kk < 4; kk++) {
                const uint32_t* bp = (const uint32_t*)(Kc + browx * 72 + kk * 16);
                mma_f16(s, af[kk][0], af[kk][1], af[kk][2], af[kk][3], bp[q], bp[q + 4]);
            }
            uint32_t p01 = ex2_f16x2(s[0] * FC, s[1] * FC);
            uint32_t p23 = ex2_f16x2(s[2] * FC, s[3] * FC);
            float2 f01 = __half22float2(*(__half2*)&p01);
            float2 f23 = __half22float2(*(__half2*)&p23);
            rp0 += f01.x + f01.y;
            rp1 += f23.x + f23.y;
            PsU[arow * 36 + nt * 4 + q] = p01;
            PsU[(arow + 8) * 36 + nt * 4 + q] = p23;
        }
        rloc0 += rp0;
        rloc1 += rp1;
        __syncthreads();   // Ps complete

        // ---- o += Ps(128x64) @ V(64x64) ----
#pragma unroll
        for (int kc = 0; kc < 4; kc++) {
            uint32_t a[4];
            ldm_x4(a, Ps + arow_lm * 72 + kc * 16 + acoff);
#pragma unroll
            for (int dtp = 0; dtp < 4; dtp++) {
                uint32_t b[4];
                ldm_x4_trans(b, Vc + (kc * 16 + brow2) * 72 + dtp * 16 + bcoff);
                mma_f16(o[2 * dtp],     a[0], a[1], a[2], a[3], b[0], b[1]);
                mma_f16(o[2 * dtp + 1], a[0], a[1], a[2], a[3], b[2], b[3]);
            }
        }
        __syncthreads();   // Ps/V reads done before refill
        if (i + 2 < 32) issue(i + 2, buf);
    }

    // ---- flush partial o (direct store) + row sums (2-way atomics) ----
    {
        const int rN = n0 + arow;
        float* Og = g_Opf[z] + rN * 512 + hc;
#pragma unroll
        for (int dt = 0; dt < 8; dt++) {
            *(float2*)&Og[dt * 8 + 2 * q] = make_float2(o[dt][0], o[dt][1]);
            *(float2*)&Og[8 * 512 + dt * 8 + 2 * q] = make_float2(o[dt][2], o[dt][3]);
        }
    }
    rloc0 += __shfl_xor_sync(FULLM, rloc0, 1);
    rloc0 += __shfl_xor_sync(FULLM, rloc0, 2);
    rloc1 += __shfl_xor_sync(FULLM, rloc1, 1);
    rloc1 += __shfl_xor_sync(FULLM, rloc1, 2);
    if (q == 0) {
        atomicAdd(&sumg[head * Nn + n0 + arow], rloc0);
        atomicAdd(&sumg[head * Nn + n0 + arow + 8], rloc1);
    }
}

// ---------------------------------------------------------------------------
// Output GEMM (fp16 mma): out = ((S0+S1) * inv) @ Wo + bias
// grid (4, 32, 2): z=0 -> o1 (slabs 2,3; csum-inv; wo1), z=1 -> o2 (slabs 0,1)
// ---------------------------------------------------------------------------
__global__ __launch_bounds__(256) void outproj_f16_kernel(Ptrs in, float* out) {
    const float *S0, *S1, *inv, *W, *bias;
    float* C;
    if (blockIdx.z == 0) {
        S0 = g_Opf[2]; S1 = g_Opf[3]; inv = g_csum;
        W = in.p[12]; bias = in.p[13]; C = out;
    } else {
        S0 = g_Opf[0]; S1 = g_Opf[1]; inv = g_rsum;
        W = in.p[14]; bias = in.p[15]; C = out + Nn * 256;
    }
    __shared__ __half As[128 * 72];
    __shared__ __half Ws[64 * 72];

    const int tid = threadIdx.x;
    const int lane = tid & 31, wid = tid >> 5;
    const int q = lane & 3, g = lane >> 2;
    const int row0 = blockIdx.y * 128;
    const int col0 = blockIdx.x * 64;
    const int brow = ((lane >> 3) & 1) * 8 + (lane & 7);
    const int bcoff = (lane >> 4) * 8;
    const int arow = wid * 16 + (lane & 7) + ((lane >> 3) & 1) * 8;
    const int acoff = (lane >> 4) * 8;

    float o[8][4];
#pragma unroll
    for (int nt = 0; nt < 8; nt++)
#pragma unroll
        for (int j = 0; j < 4; j++) o[nt][j] = 0.f;

    for (int k0 = 0; k0 < 512; k0 += 64) {
        const int head = k0 >> 6;
        __syncthreads();
        // A staging: merge two fp32 slabs, normalize -> fp16
#pragma unroll
        for (int it = 0; it < 4; it++) {
            int j = tid + it * 256;
            int rr = j >> 3, c8 = j & 7;
            int idx = (row0 + rr) * 512 + k0 + c8 * 8;
            float iv = inv[head * Nn + row0 + rr];
            float4 a0 = *(const float4*)&S0[idx];
            float4 a1 = *(const float4*)&S0[idx + 4];
            float4 b0 = *(const float4*)&S1[idx];
            float4 b1 = *(const float4*)&S1[idx + 4];
            a0.x = (a0.x + b0.x) * iv; a0.y = (a0.y + b0.y) * iv;
            a0.z = (a0.z + b0.z) * iv; a0.w = (a0.w + b0.w) * iv;
            a1.x = (a1.x + b1.x) * iv; a1.y = (a1.y + b1.y) * iv;
            a1.z = (a1.z + b1.z) * iv; a1.w = (a1.w + b1.w) * iv;
            *(uint4*)&As[rr * 72 + c8 * 8] = pack8h(a0, a1);
        }
#pragma unroll
        for (int it = 0; it < 2; it++) {
            int j = tid + it * 256;
            int rr = j >> 3, c8 = j & 7;
            const float* src = &W[(k0 + rr) * 256 + col0 + c8 * 8];
            *(uint4*)&Ws[rr * 72 + c8 * 8] =
                pack8h(*(const float4*)src, *(const float4*)(src + 4));
        }
        __syncthreads();
#pragma unroll
        for (int kk = 0; kk < 4; kk++) {
            uint32_t a[4];
            ldm_x4(a, As + arow * 72 + kk * 16 + acoff);
#pragma unroll
            for (int dtp = 0; dtp < 4; dtp++) {
                uint32_t b[4];
                ldm_x4_trans(b, Ws + (kk * 16 + brow) * 72 + dtp * 16 + bcoff);
                mma_f16(o[2 * dtp],     a[0], a[1], a[2], a[3], b[0], b[1]);
                mma_f16(o[2 * dtp + 1], a[0], a[1], a[2], a[3], b[2], b[3]);
            }
        }
    }

    const int r = row0 + wid * 16 + g;
#pragma unroll
    for (int nt = 0; nt < 8; nt++) {
        int c = col0 + nt * 8 + 2 * q;
        float b0 = bias[c], b1 = bias[c + 1];
        *(float2*)&C[r * 256 + c] = make_float2(o[nt][0] + b0, o[nt][1] + b1);
        *(float2*)&C[(r + 8) * 256 + c] = make_float2(o[nt][2] + b0, o[nt][3] + b1);
    }
}

extern "C" void kernel_launch(void* const* d_in, const int* in_sizes, int n_in,
                              void* d_out, int out_size) {
    Ptrs ptrs;
    for (int i = 0; i < 16; i++) ptrs.p[i] = (const float*)d_in[i];
    float* out = (float*)d_out;

    const int fused_smem = 27648 * 2;   // 54 KB
    cudaFuncSetAttribute(fused_dir_kernel, cudaFuncAttributeMaxDynamicSharedMemorySize,
                         fused_smem);

    zero_kernel<<<64, 256>>>();
    {
        dim3 grid(512 / 64, Nn / 128, 4);
        proj_f16_kernel<<<grid, 256>>>(ptrs);
    }
    {
        dim3 grid(Nn / 128, NHEADS, 4);
        fused_dir_kernel<<<grid, 256, fused_smem>>>();
    }
    recip_kernel<<<128, 256>>>();
    {
        dim3 grid(256 / 64, Nn / 128, 2);
        outproj_f16_kernel<<<grid, 256>>>(ptrs, out);
    }
}

// round 9
// speedup vs baseline: 1.3624x; 1.1176x over previous
#include <cuda_runtime.h>
#include <cuda_fp16.h>
#include <math.h>
#include <stdint.h>

#define Nn 4096
#define NHEADS 8
#define SQFC 0.42466090f   // sqrt(SCALE * log2(e))
#define FULLM 0xffffffffu

// fp16 projections (K1/K2 pre-scaled by SQFC)
__device__ __half g_K1H[Nn * 512];
__device__ __half g_K2H[Nn * 512];
__device__ __half g_V1H[Nn * 512];
__device__ __half g_V2H[Nn * 512];
// fp32 partial attention outputs: slab z = dir*2 + ks
__device__ float g_Opf[4][Nn * 512];
__device__ float g_rsum[NHEADS * Nn];
__device__ float g_csum[NHEADS * Nn];

struct Ptrs {
    const float* p[16];
};

__device__ __forceinline__ void mma_f16(float c[4],
                                        uint32_t a0, uint32_t a1, uint32_t a2, uint32_t a3,
                                        uint32_t b0, uint32_t b1) {
    asm volatile(
        "mma.sync.aligned.m16n8k16.row.col.f32.f16.f16.f32 "
        "{%0,%1,%2,%3}, {%4,%5,%6,%7}, {%8,%9}, {%0,%1,%2,%3};\n"
        : "+f"(c[0]), "+f"(c[1]), "+f"(c[2]), "+f"(c[3])
        : "r"(a0), "r"(a1), "r"(a2), "r"(a3), "r"(b0), "r"(b1));
}

__device__ __forceinline__ void ldm_x4(uint32_t r[4], const void* ptr) {
    uint32_t addr = (uint32_t)__cvta_generic_to_shared(ptr);
    asm volatile("ldmatrix.sync.aligned.m8n8.x4.shared.b16 {%0,%1,%2,%3}, [%4];"
                 : "=r"(r[0]), "=r"(r[1]), "=r"(r[2]), "=r"(r[3]) : "r"(addr));
}

__device__ __forceinline__ void ldm_x4_trans(uint32_t r[4], const void* ptr) {
    uint32_t addr = (uint32_t)__cvta_generic_to_shared(ptr);
    asm volatile("ldmatrix.sync.aligned.m8n8.x4.trans.shared.b16 {%0,%1,%2,%3}, [%4];"
                 : "=r"(r[0]), "=r"(r[1]), "=r"(r[2]), "=r"(r[3]) : "r"(addr));
}

__device__ __forceinline__ void cp16(void* smem_dst, const void* gsrc) {
    uint32_t d = (uint32_t)__cvta_generic_to_shared(smem_dst);
    asm volatile("cp.async.cg.shared.global [%0], [%1], 16;" :: "r"(d), "l"(gsrc));
}

__device__ __forceinline__ uint32_t ex2_f16x2(float a, float b) {
    __half2 h = __floats2half2_rn(a, b);
    uint32_t r;
    asm("ex2.approx.f16x2 %0, %1;" : "=r"(r) : "r"(*(uint32_t*)&h));
    return r;
}

__device__ __forceinline__ uint4 pack8h(float4 v0, float4 v1) {
    uint4 u;
    __half2* h = (__half2*)&u;
    h[0] = __floats2half2_rn(v0.x, v0.y);
    h[1] = __floats2half2_rn(v0.z, v0.w);
    h[2] = __floats2half2_rn(v1.x, v1.y);
    h[3] = __floats2half2_rn(v1.z, v1.w);
    return u;
}

// ---------------------------------------------------------------------------
__global__ void zero_kernel() {
    int i = blockIdx.x * 256 + threadIdx.x;
    float4 z = make_float4(0.f, 0.f, 0.f, 0.f);
    if (i < 8192) ((float4*)g_rsum)[i] = z;
    else          ((float4*)g_csum)[i - 8192] = z;
}

__global__ void recip_kernel() {
    int i = blockIdx.x * 256 + threadIdx.x;
    g_rsum[i] = 1.0f / g_rsum[i];
    g_csum[i] = 1.0f / g_csum[i];
}

// ---------------------------------------------------------------------------
// Projection (fp16 mma): C = A @ W + bias -> fp16; K1/K2 scaled by SQFC.
// grid (8, 32, 4), 256 thr.
// ---------------------------------------------------------------------------
__global__ __launch_bounds__(256) void proj_f16_kernel(Ptrs in) {
    const float *A, *W, *bias;
    __half* C;
    float sc;
    switch (blockIdx.z) {
        case 0: A = in.p[0]; W = in.p[4];  bias = in.p[5];  C = g_K1H; sc = SQFC; break;
        case 1: A = in.p[1]; W = in.p[6];  bias = in.p[7];  C = g_V1H; sc = 1.0f; break;
        case 2: A = in.p[2]; W = in.p[8];  bias = in.p[9];  C = g_K2H; sc = SQFC; break;
        default:A = in.p[3]; W = in.p[10]; bias = in.p[11]; C = g_V2H; sc = 1.0f; break;
    }
    __shared__ __half As[128 * 72];
    __shared__ __half Ws[64 * 72];

    const int tid = threadIdx.x;
    const int lane = tid & 31, wid = tid >> 5;
    const int q = lane & 3, g = lane >> 2;
    const int row0 = blockIdx.y * 128;
    const int col0 = blockIdx.x * 64;
    const int brow = ((lane >> 3) & 1) * 8 + (lane & 7);
    const int bcoff = (lane >> 4) * 8;
    const int arow = wid * 16 + (lane & 7) + ((lane >> 3) & 1) * 8;
    const int acoff = (lane >> 4) * 8;

    float o[8][4];
#pragma unroll
    for (int nt = 0; nt < 8; nt++)
#pragma unroll
        for (int j = 0; j < 4; j++) o[nt][j] = 0.f;

    for (int k0 = 0; k0 < 256; k0 += 64) {
        __syncthreads();
#pragma unroll
        for (int it = 0; it < 4; it++) {
            int j = tid + it * 256;
            int rr = j >> 3, c8 = j & 7;
            const float* src = &A[(row0 + rr) * 256 + k0 + c8 * 8];
            *(uint4*)&As[rr * 72 + c8 * 8] =
                pack8h(*(const float4*)src, *(const float4*)(src + 4));
        }
#pragma unroll
        for (int it = 0; it < 2; it++) {
            int j = tid + it * 256;
            int rr = j >> 3, c8 = j & 7;
            const float* src = &W[(k0 + rr) * 512 + col0 + c8 * 8];
            *(uint4*)&Ws[rr * 72 + c8 * 8] =
                pack8h(*(const float4*)src, *(const float4*)(src + 4));
        }
        __syncthreads();
#pragma unroll
        for (int kk = 0; kk < 4; kk++) {
            uint32_t a[4];
            ldm_x4(a, As + arow * 72 + kk * 16 + acoff);
#pragma unroll
            for (int dtp = 0; dtp < 4; dtp++) {
                uint32_t b[4];
                ldm_x4_trans(b, Ws + (kk * 16 + brow) * 72 + dtp * 16 + bcoff);
                mma_f16(o[2 * dtp],     a[0], a[1], a[2], a[3], b[0], b[1]);
                mma_f16(o[2 * dtp + 1], a[0], a[1], a[2], a[3], b[2], b[3]);
            }
        }
    }

    const int r = row0 + wid * 16 + g;
#pragma unroll
    for (int nt = 0; nt < 8; nt++) {
        int c = col0 + nt * 8 + 2 * q;
        float b0 = bias[c], b1 = bias[c + 1];
        __half2 h0 = __floats2half2_rn((o[nt][0] + b0) * sc, (o[nt][1] + b1) * sc);
        __half2 h1 = __floats2half2_rn((o[nt][2] + b0) * sc, (o[nt][3] + b1) * sc);
        *(uint32_t*)&C[r * 512 + c] = *(uint32_t*)&h0;
        *(uint32_t*)&C[(r + 8) * 512 + c] = *(uint32_t*)&h1;
    }
}

// ---------------------------------------------------------------------------
// Fused dual attention (one direction per CTA, k-split x2):
// 4-stage cp.async K/V pipeline, 1 block-sync per iter, warp-private Ps,
// ldsm-based S operands, exp via ex2.f16x2 (scale pre-folded into K1/K2).
// grid (32, 8, 4), 256 thr, 90KB smem, occ 2.
// ---------------------------------------------------------------------------
__global__ __launch_bounds__(256, 2) void fused_dir_kernel() {
    extern __shared__ __half sm[];
    __half* Ps = sm;                 // [128][72], warp-private rows; Q staging at init
    __half* Kb = sm + 9216;          // 4 x [64][72]
    __half* Vb = sm + 9216 + 4 * 4608;
    uint32_t* PsU = (uint32_t*)sm;   // stride 36 words

    const int n0 = blockIdx.x * 128;
    const int head = blockIdx.y;
    const int hc = head * 64;
    const int z = blockIdx.z;
    const int dir = z >> 1;
    const int ks = z & 1;

    const __half* Qg = dir ? g_K2H : g_K1H;
    const __half* Kg = dir ? g_K1H : g_K2H;
    const __half* Vg = dir ? g_V1H : g_V2H;
    float* sumg = dir ? g_csum : g_rsum;

    const int tid = threadIdx.x;
    const int lane = tid & 31, wid = tid >> 5;
    const int q = lane & 3, g = lane >> 2;
    const int arow_lm = wid * 16 + (lane & 7) + ((lane >> 3) & 1) * 8;
    const int acoff = (lane >> 4) * 8;
    const int brow2 = ((lane >> 3) & 1) * 8 + (lane & 7);   // also S-phase B rows
    const int bcoff = (lane >> 4) * 8;
    const int arow = wid * 16 + g;

    // ---- stage Q, build A-fragments ----
#pragma unroll
    for (int it = 0; it < 4; it++) {
        int j = tid + it * 256;
        int rr = j >> 3, c8 = j & 7;
        cp16(Ps + rr * 72 + c8 * 8, Qg + (n0 + rr) * 512 + hc + c8 * 8);
    }
    asm volatile("cp.async.commit_group;" ::: "memory");
    asm volatile("cp.async.wait_group 0;" ::: "memory");
    __syncthreads();

    uint32_t af[4][4];
#pragma unroll
    for (int kk = 0; kk < 4; kk++)
        ldm_x4(af[kk], Ps + arow_lm * 72 + kk * 16 + acoff);
    __syncthreads();   // Ps free

    auto issue = [&](int s) {
        const int m0 = (ks * 32 + s) * 64;
        __half* Kd = Kb + (s & 3) * 4608;
        __half* Vd = Vb + (s & 3) * 4608;
#pragma unroll
        for (int it = 0; it < 2; it++) {
            int j = tid + it * 256;
            int rr = j >> 3, c8 = j & 7;
            cp16(Kd + rr * 72 + c8 * 8, Kg + (m0 + rr) * 512 + hc + c8 * 8);
            cp16(Vd + rr * 72 + c8 * 8, Vg + (m0 + rr) * 512 + hc + c8 * 8);
        }
        asm volatile("cp.async.commit_group;" ::: "memory");
    };

    issue(0);
    issue(1);
    issue(2);

    float o[8][4];
#pragma unroll
    for (int dt = 0; dt < 8; dt++)
#pragma unroll
        for (int j = 0; j < 4; j++) o[dt][j] = 0.f;
    float rloc0 = 0.f, rloc1 = 0.f;

    for (int i = 0; i < 32; i++) {
        if (i < 30)       asm volatile("cp.async.wait_group 2;" ::: "memory");
        else if (i == 30) asm volatile("cp.async.wait_group 1;" ::: "memory");
        else              asm volatile("cp.async.wait_group 0;" ::: "memory");
        __syncthreads();   // stage i visible; slot (i-1)&3 free; prev Ps reads done

        if (i + 3 < 32) issue(i + 3);   // targets slot (i-1)&3

        const __half* Kc = Kb + (i & 3) * 4608;
        const __half* Vc = Vb + (i & 3) * 4608;

        // ---- S (warp: 16 rows x 64 keys) + exp -> warp-private Ps rows ----
#pragma unroll
        for (int nt2 = 0; nt2 < 4; nt2++) {
            float s0[4] = {0.f, 0.f, 0.f, 0.f};
            float s1[4] = {0.f, 0.f, 0.f, 0.f};
#pragma unroll
            for (int kk = 0; kk < 4; kk++) {
                uint32_t bq[4];
                ldm_x4(bq, Kc + (nt2 * 16 + brow2) * 72 + kk * 16 + bcoff);
                mma_f16(s0, af[kk][0], af[kk][1], af[kk][2], af[kk][3], bq[0], bq[2]);
                mma_f16(s1, af[kk][0], af[kk][1], af[kk][2], af[kk][3], bq[1], bq[3]);
            }
            uint32_t pA01 = ex2_f16x2(s0[0], s0[1]);
            uint32_t pA23 = ex2_f16x2(s0[2], s0[3]);
            uint32_t pB01 = ex2_f16x2(s1[0], s1[1]);
            uint32_t pB23 = ex2_f16x2(s1[2], s1[3]);
            float2 fA01 = __half22float2(*(__half2*)&pA01);
            float2 fA23 = __half22float2(*(__half2*)&pA23);
            float2 fB01 = __half22float2(*(__half2*)&pB01);
            float2 fB23 = __half22float2(*(__half2*)&pB23);
            rloc0 += fA01.x + fA01.y + fB01.x + fB01.y;
            rloc1 += fA23.x + fA23.y + fB23.x + fB23.y;
            PsU[arow * 36 + (2 * nt2) * 4 + q] = pA01;
            PsU[(arow + 8) * 36 + (2 * nt2) * 4 + q] = pA23;
            PsU[arow * 36 + (2 * nt2 + 1) * 4 + q] = pB01;
            PsU[(arow + 8) * 36 + (2 * nt2 + 1) * 4 + q] = pB23;
        }
        __syncwarp();   // own-warp Ps rows visible to own-warp ldsm

        // ---- o += Ps(own 16 rows x 64) @ V(64x64) ----
#pragma unroll
        for (int kc = 0; kc < 4; kc++) {
            uint32_t a[4];
            ldm_x4(a, Ps + arow_lm * 72 + kc * 16 + acoff);
#pragma unroll
            for (int dtp = 0; dtp < 4; dtp++) {
                uint32_t b[4];
                ldm_x4_trans(b, Vc + (kc * 16 + brow2) * 72 + dtp * 16 + bcoff);
                mma_f16(o[2 * dtp],     a[0], a[1], a[2], a[3], b[0], b[1]);
                mma_f16(o[2 * dtp + 1], a[0], a[1], a[2], a[3], b[2], b[3]);
            }
        }
    }

    // ---- flush partial o (direct store) + row sums ----
    {
        const int rN = n0 + arow;
        float* Og = g_Opf[z] + rN * 512 + hc;
#pragma unroll
        for (int dt = 0; dt < 8; dt++) {
            *(float2*)&Og[dt * 8 + 2 * q] = make_float2(o[dt][0], o[dt][1]);
            *(float2*)&Og[8 * 512 + dt * 8 + 2 * q] = make_float2(o[dt][2], o[dt][3]);
        }
    }
    rloc0 += __shfl_xor_sync(FULLM, rloc0, 1);
    rloc0 += __shfl_xor_sync(FULLM, rloc0, 2);
    rloc1 += __shfl_xor_sync(FULLM, rloc1, 1);
    rloc1 += __shfl_xor_sync(FULLM, rloc1, 2);
    if (q == 0) {
        atomicAdd(&sumg[head * Nn + n0 + arow], rloc0);
        atomicAdd(&sumg[head * Nn + n0 + arow + 8], rloc1);
    }
}

// ---------------------------------------------------------------------------
// Output GEMM (fp16 mma): out = ((S0+S1) * inv) @ Wo + bias
// grid (4, 32, 2).
// ---------------------------------------------------------------------------
__global__ __launch_bounds__(256) void outproj_f16_kernel(Ptrs in, float* out) {
    const float *S0, *S1, *inv, *W, *bias;
    float* C;
    if (blockIdx.z == 0) {
        S0 = g_Opf[2]; S1 = g_Opf[3]; inv = g_csum;
        W = in.p[12]; bias = in.p[13]; C = out;
    } else {
        S0 = g_Opf[0]; S1 = g_Opf[1]; inv = g_rsum;
        W = in.p[14]; bias = in.p[15]; C = out + Nn * 256;
    }
    __shared__ __half As[128 * 72];
    __shared__ __half Ws[64 * 72];

    const int tid = threadIdx.x;
    const int lane = tid & 31, wid = tid >> 5;
    const int q = lane & 3, g = lane >> 2;
    const int row0 = blockIdx.y * 128;
    const int col0 = blockIdx.x * 64;
    const int brow = ((lane >> 3) & 1) * 8 + (lane & 7);
    const int bcoff = (lane >> 4) * 8;
    const int arow = wid * 16 + (lane & 7) + ((lane >> 3) & 1) * 8;
    const int acoff = (lane >> 4) * 8;

    float o[8][4];
#pragma unroll
    for (int nt = 0; nt < 8; nt++)
#pragma unroll
        for (int j = 0; j < 4; j++) o[nt][j] = 0.f;

    for (int k0 = 0; k0 < 512; k0 += 64) {
        const int head = k0 >> 6;
        __syncthreads();
#pragma unroll
        for (int it = 0; it < 4; it++) {
            int j = tid + it * 256;
            int rr = j >> 3, c8 = j & 7;
            int idx = (row0 + rr) * 512 + k0 + c8 * 8;
            float iv = inv[head * Nn + row0 + rr];
            float4 a0 = *(const float4*)&S0[idx];
            float4 a1 = *(const float4*)&S0[idx + 4];
            float4 b0 = *(const float4*)&S1[idx];
            float4 b1 = *(const float4*)&S1[idx + 4];
            a0.x = (a0.x + b0.x) * iv; a0.y = (a0.y + b0.y) * iv;
            a0.z = (a0.z + b0.z) * iv; a0.w = (a0.w + b0.w) * iv;
            a1.x = (a1.x + b1.x) * iv; a1.y = (a1.y + b1.y) * iv;
            a1.z = (a1.z + b1.z) * iv; a1.w = (a1.w + b1.w) * iv;
            *(uint4*)&As[rr * 72 + c8 * 8] = pack8h(a0, a1);
        }
#pragma unroll
        for (int it = 0; it < 2; it++) {
            int j = tid + it * 256;
            int rr = j >> 3, c8 = j & 7;
            const float* src = &W[(k0 + rr) * 256 + col0 + c8 * 8];
            *(uint4*)&Ws[rr * 72 + c8 * 8] =
                pack8h(*(const float4*)src, *(const float4*)(src + 4));
        }
        __syncthreads();
#pragma unroll
        for (int kk = 0; kk < 4; kk++) {
            uint32_t a[4];
            ldm_x4(a, As + arow * 72 + kk * 16 + acoff);
#pragma unroll
            for (int dtp = 0; dtp < 4; dtp++) {
                uint32_t b[4];
                ldm_x4_trans(b, Ws + (kk * 16 + brow) * 72 + dtp * 16 + bcoff);
                mma_f16(o[2 * dtp],     a[0], a[1], a[2], a[3], b[0], b[1]);
                mma_f16(o[2 * dtp + 1], a[0], a[1], a[2], a[3], b[2], b[3]);
            }
        }
    }

    const int r = row0 + wid * 16 + g;
#pragma unroll
    for (int nt = 0; nt < 8; nt++) {
        int c = col0 + nt * 8 + 2 * q;
        float b0 = bias[c], b1 = bias[c + 1];
        *(float2*)&C[r * 256 + c] = make_float2(o[nt][0] + b0, o[nt][1] + b1);
        *(float2*)&C[(r + 8) * 256 + c] = make_float2(o[nt][2] + b0, o[nt][3] + b1);
    }
}

extern "C" void kernel_launch(void* const* d_in, const int* in_sizes, int n_in,
                              void* d_out, int out_size) {
    Ptrs ptrs;
    for (int i = 0; i < 16; i++) ptrs.p[i] = (const float*)d_in[i];
    float* out = (float*)d_out;

    const int fused_smem = (9216 + 8 * 4608) * 2;   // 90 KB
    cudaFuncSetAttribute(fused_dir_kernel, cudaFuncAttributeMaxDynamicSharedMemorySize,
                         fused_smem);

    zero_kernel<<<64, 256>>>();
    {
        dim3 grid(512 / 64, Nn / 128, 4);
        proj_f16_kernel<<<grid, 256>>>(ptrs);
    }
    {
        dim3 grid(Nn / 128, NHEADS, 4);
        fused_dir_kernel<<<grid, 256, fused_smem>>>();
    }
    recip_kernel<<<128, 256>>>();
    {
        dim3 grid(256 / 64, Nn / 128, 2);
        outproj_f16_kernel<<<grid, 256>>>(ptrs, out);
    }
}

// round 11
// speedup vs baseline: 1.4314x; 1.0507x over previous
#include <cuda_runtime.h>
#include <cuda_fp16.h>
#include <math.h>
#include <stdint.h>

#define Nn 4096
#define NHEADS 8
#define SQFC 0.42466090f   // sqrt(SCALE * log2(e))
#define FULLM 0xffffffffu

// fp16 projections (K1/K2 pre-scaled by SQFC)
__device__ __half g_K1H[Nn * 512];
__device__ __half g_K2H[Nn * 512];
__device__ __half g_V1H[Nn * 512];
__device__ __half g_V2H[Nn * 512];
// fp16 partial attention outputs: slab z = dir*2 + ks
__device__ __half g_Oph[4][Nn * 512];
// per-slab row-sum partials (direct store, no atomics/zeroing)
__device__ float g_sumP[4][NHEADS * Nn];
__device__ float g_rsum[NHEADS * Nn];   // holds 1/rowsum after recip
__device__ float g_csum[NHEADS * Nn];   // holds 1/colsum after recip

struct Ptrs {
    const float* p[16];
};

__device__ __forceinline__ void mma_f16(float c[4],
                                        uint32_t a0, uint32_t a1, uint32_t a2, uint32_t a3,
                                        uint32_t b0, uint32_t b1) {
    asm volatile(
        "mma.sync.aligned.m16n8k16.row.col.f32.f16.f16.f32 "
        "{%0,%1,%2,%3}, {%4,%5,%6,%7}, {%8,%9}, {%0,%1,%2,%3};\n"
        : "+f"(c[0]), "+f"(c[1]), "+f"(c[2]), "+f"(c[3])
        : "r"(a0), "r"(a1), "r"(a2), "r"(a3), "r"(b0), "r"(b1));
}

// f16-accumulator variant: D/C are 2 packed f16x2 regs
__device__ __forceinline__ void mma_f16h(uint32_t c[2],
                                         uint32_t a0, uint32_t a1, uint32_t a2, uint32_t a3,
                                         uint32_t b0, uint32_t b1) {
    asm volatile(
        "mma.sync.aligned.m16n8k16.row.col.f16.f16.f16.f16 "
        "{%0,%1}, {%2,%3,%4,%5}, {%6,%7}, {%0,%1};\n"
        : "+r"(c[0]), "+r"(c[1])
        : "r"(a0), "r"(a1), "r"(a2), "r"(a3), "r"(b0), "r"(b1));
}

__device__ __forceinline__ void ldm_x4(uint32_t r[4], const void* ptr) {
    uint32_t addr = (uint32_t)__cvta_generic_to_shared(ptr);
    asm volatile("ldmatrix.sync.aligned.m8n8.x4.shared.b16 {%0,%1,%2,%3}, [%4];"
                 : "=r"(r[0]), "=r"(r[1]), "=r"(r[2]), "=r"(r[3]) : "r"(addr));
}

__device__ __forceinline__ void ldm_x4_trans(uint32_t r[4], const void* ptr) {
    uint32_t addr = (uint32_t)__cvta_generic_to_shared(ptr);
    asm volatile("ldmatrix.sync.aligned.m8n8.x4.trans.shared.b16 {%0,%1,%2,%3}, [%4];"
                 : "=r"(r[0]), "=r"(r[1]), "=r"(r[2]), "=r"(r[3]) : "r"(addr));
}

__device__ __forceinline__ void cp16(void* smem_dst, const void* gsrc) {
    uint32_t d = (uint32_t)__cvta_generic_to_shared(smem_dst);
    asm volatile("cp.async.cg.shared.global [%0], [%1], 16;" :: "r"(d), "l"(gsrc));
}

__device__ __forceinline__ uint32_t ex2p(uint32_t h2) {
    uint32_t r;
    asm("ex2.approx.f16x2 %0, %1;" : "=r"(r) : "r"(h2));
    return r;
}

__device__ __forceinline__ uint4 pack8h(float4 v0, float4 v1) {
    uint4 u;
    __half2* h = (__half2*)&u;
    h[0] = __floats2half2_rn(v0.x, v0.y);
    h[1] = __floats2half2_rn(v0.z, v0.w);
    h[2] = __floats2half2_rn(v1.x, v1.y);
    h[3] = __floats2half2_rn(v1.z, v1.w);
    return u;
}

// ---------------------------------------------------------------------------
// merge row-sum partials -> reciprocals
// ---------------------------------------------------------------------------
__global__ void recip_kernel() {
    int i = blockIdx.x * 256 + threadIdx.x;   // 32768
    g_rsum[i] = 1.0f / (g_sumP[0][i] + g_sumP[1][i]);
    g_csum[i] = 1.0f / (g_sumP[2][i] + g_sumP[3][i]);
}

// ---------------------------------------------------------------------------
// Projection (fp16 mma): C = A @ W + bias -> fp16; K1/K2 scaled by SQFC.
// grid (8, 32, 4), 256 thr.
// ---------------------------------------------------------------------------
__global__ __launch_bounds__(256) void proj_f16_kernel(Ptrs in) {
    const float *A, *W, *bias;
    __half* C;
    float sc;
    switch (blockIdx.z) {
        case 0: A = in.p[0]; W = in.p[4];  bias = in.p[5];  C = g_K1H; sc = SQFC; break;
        case 1: A = in.p[1]; W = in.p[6];  bias = in.p[7];  C = g_V1H; sc = 1.0f; break;
        case 2: A = in.p[2]; W = in.p[8];  bias = in.p[9];  C = g_K2H; sc = SQFC; break;
        default:A = in.p[3]; W = in.p[10]; bias = in.p[11]; C = g_V2H; sc = 1.0f; break;
    }
    __shared__ __half As[128 * 72];
    __shared__ __half Ws[64 * 72];

    const int tid = threadIdx.x;
    const int lane = tid & 31, wid = tid >> 5;
    const int q = lane & 3, g = lane >> 2;
    const int row0 = blockIdx.y * 128;
    const int col0 = blockIdx.x * 64;
    const int brow = ((lane >> 3) & 1) * 8 + (lane & 7);
    const int bcoff = (lane >> 4) * 8;
    const int arow = wid * 16 + (lane & 7) + ((lane >> 3) & 1) * 8;
    const int acoff = (lane >> 4) * 8;

    float o[8][4];
#pragma unroll
    for (int nt = 0; nt < 8; nt++)
#pragma unroll
        for (int j = 0; j < 4; j++) o[nt][j] = 0.f;

    for (int k0 = 0; k0 < 256; k0 += 64) {
        __syncthreads();
#pragma unroll
        for (int it = 0; it < 4; it++) {
            int j = tid + it * 256;
            int rr = j >> 3, c8 = j & 7;
            const float* src = &A[(row0 + rr) * 256 + k0 + c8 * 8];
            *(uint4*)&As[rr * 72 + c8 * 8] =
                pack8h(*(const float4*)src, *(const float4*)(src + 4));
        }
#pragma unroll
        for (int it = 0; it < 2; it++) {
            int j = tid + it * 256;
            int rr = j >> 3, c8 = j & 7;
            const float* src = &W[(k0 + rr) * 512 + col0 + c8 * 8];
            *(uint4*)&Ws[rr * 72 + c8 * 8] =
                pack8h(*(const float4*)src, *(const float4*)(src + 4));
        }
        __syncthreads();
#pragma unroll
        for (int kk = 0; kk < 4; kk++) {
            uint32_t a[4];
            ldm_x4(a, As + arow * 72 + kk * 16 + acoff);
#pragma unroll
            for (int dtp = 0; dtp < 4; dtp++) {
                uint32_t b[4];
                ldm_x4_trans(b, Ws + (kk * 16 + brow) * 72 + dtp * 16 + bcoff);
                mma_f16(o[2 * dtp],     a[0], a[1], a[2], a[3], b[0], b[1]);
                mma_f16(o[2 * dtp + 1], a[0], a[1], a[2], a[3], b[2], b[3]);
            }
        }
    }

    const int r = row0 + wid * 16 + g;
#pragma unroll
    for (int nt = 0; nt < 8; nt++) {
        int c = col0 + nt * 8 + 2 * q;
        float b0 = bias[c], b1 = bias[c + 1];
        __half2 h0 = __floats2half2_rn((o[nt][0] + b0) * sc, (o[nt][1] + b1) * sc);
        __half2 h1 = __floats2half2_rn((o[nt][2] + b0) * sc, (o[nt][3] + b1) * sc);
        *(uint32_t*)&C[r * 512 + c] = *(uint32_t*)&h0;
        *(uint32_t*)&C[(r + 8) * 512 + c] = *(uint32_t*)&h1;
    }
}

// ---------------------------------------------------------------------------
// Fused dual attention (R9 structure + f16 S-accum + direct-store sums + fp16 O):
// grid (32, 8, 4): z = dir*2 + ks. 4-stage cp.async pipeline, 1 block-sync/iter,
// warp-private Ps, exp via ex2.f16x2 directly on packed f16 accumulators.
// ---------------------------------------------------------------------------
__global__ __launch_bounds__(256, 2) void fused_dir_kernel() {
    extern __shared__ __half sm[];
    __half* Ps = sm;                 // [128][72], warp-private rows; Q staging at init
    __half* Kb = sm + 9216;          // 4 x [64][72]
    __half* Vb = sm + 9216 + 4 * 4608;
    uint32_t* PsU = (uint32_t*)sm;   // stride 36 words

    const int n0 = blockIdx.x * 128;
    const int head = blockIdx.y;
    const int hc = head * 64;
    const int z = blockIdx.z;
    const int dir = z >> 1;
    const int ks = z & 1;

    const __half* Qg = dir ? g_K2H : g_K1H;
    const __half* Kg = dir ? g_K1H : g_K2H;
    const __half* Vg = dir ? g_V1H : g_V2H;

    const int tid = threadIdx.x;
    const int lane = tid & 31, wid = tid >> 5;
    const int q = lane & 3, g = lane >> 2;
    const int arow_lm = wid * 16 + (lane & 7) + ((lane >> 3) & 1) * 8;
    const int acoff = (lane >> 4) * 8;
    const int brow2 = ((lane >> 3) & 1) * 8 + (lane & 7);
    const int bcoff = (lane >> 4) * 8;
    const int arow = wid * 16 + g;

    // ---- stage Q, build A-fragments ----
#pragma unroll
    for (int it = 0; it < 4; it++) {
        int j = tid + it * 256;
        int rr = j >> 3, c8 = j & 7;
        cp16(Ps + rr * 72 + c8 * 8, Qg + (n0 + rr) * 512 + hc + c8 * 8);
    }
    asm volatile("cp.async.commit_group;" ::: "memory");
    asm volatile("cp.async.wait_group 0;" ::: "memory");
    __syncthreads();

    uint32_t af[4][4];
#pragma unroll
    for (int kk = 0; kk < 4; kk++)
        ldm_x4(af[kk], Ps + arow_lm * 72 + kk * 16 + acoff);
    __syncthreads();   // Ps free

    auto issue = [&](int s) {
        const int m0 = (ks * 32 + s) * 64;
        __half* Kd = Kb + (s & 3) * 4608;
        __half* Vd = Vb + (s & 3) * 4608;
#pragma unroll
        for (int it = 0; it < 2; it++) {
            int j = tid + it * 256;
            int rr = j >> 3, c8 = j & 7;
            cp16(Kd + rr * 72 + c8 * 8, Kg + (m0 + rr) * 512 + hc + c8 * 8);
            cp16(Vd + rr * 72 + c8 * 8, Vg + (m0 + rr) * 512 + hc + c8 * 8);
        }
        asm volatile("cp.async.commit_group;" ::: "memory");
    };

    issue(0);
    issue(1);
    issue(2);

    float o[8][4];
#pragma unroll
    for (int dt = 0; dt < 8; dt++)
#pragma unroll
        for (int j = 0; j < 4; j++) o[dt][j] = 0.f;
    float rloc0 = 0.f, rloc1 = 0.f;

    for (int i = 0; i < 32; i++) {
        if (i < 30)       asm volatile("cp.async.wait_group 2;" ::: "memory");
        else if (i == 30) asm volatile("cp.async.wait_group 1;" ::: "memory");
        else              asm volatile("cp.async.wait_group 0;" ::: "memory");
        __syncthreads();   // stage i visible; slot (i-1)&3 free; prev Ps reads done

        if (i + 3 < 32) issue(i + 3);

        const __half* Kc = Kb + (i & 3) * 4608;
        const __half* Vc = Vb + (i & 3) * 4608;

        // ---- S (f16 accum, packed) + exp -> warp-private Ps rows ----
#pragma unroll
        for (int nt2 = 0; nt2 < 4; nt2++) {
            uint32_t s0[2] = {0u, 0u};
            uint32_t s1[2] = {0u, 0u};
#pragma unroll
            for (int kk = 0; kk < 4; kk++) {
                uint32_t bq[4];
                ldm_x4(bq, Kc + (nt2 * 16 + brow2) * 72 + kk * 16 + bcoff);
                mma_f16h(s0, af[kk][0], af[kk][1], af[kk][2], af[kk][3], bq[0], bq[2]);
                mma_f16h(s1, af[kk][0], af[kk][1], af[kk][2], af[kk][3], bq[1], bq[3]);
            }
            uint32_t pA01 = ex2p(s0[0]);
            uint32_t pA23 = ex2p(s0[1]);
            uint32_t pB01 = ex2p(s1[0]);
            uint32_t pB23 = ex2p(s1[1]);
            __half2 hA = __hadd2(*(__half2*)&pA01, *(__half2*)&pB01);
            __half2 hB = __hadd2(*(__half2*)&pA23, *(__half2*)&pB23);
            float2 fA = __half22float2(hA);
            float2 fB = __half22float2(hB);
            rloc0 += fA.x + fA.y;
            rloc1 += fB.x + fB.y;
            PsU[arow * 36 + (2 * nt2) * 4 + q] = pA01;
            PsU[(arow + 8) * 36 + (2 * nt2) * 4 + q] = pA23;
            PsU[arow * 36 + (2 * nt2 + 1) * 4 + q] = pB01;
            PsU[(arow + 8) * 36 + (2 * nt2 + 1) * 4 + q] = pB23;
        }
        __syncwarp();   // own-warp Ps rows visible to own-warp ldsm

        // ---- o += Ps(own 16 rows x 64) @ V(64x64), f32 accum ----
#pragma unroll
        for (int kc = 0; kc < 4; kc++) {
            uint32_t a[4];
            ldm_x4(a, Ps + arow_lm * 72 + kc * 16 + acoff);
#pragma unroll
            for (int dtp = 0; dtp < 4; dtp++) {
                uint32_t b[4];
                ldm_x4_trans(b, Vc + (kc * 16 + brow2) * 72 + dtp * 16 + bcoff);
                mma_f16(o[2 * dtp],     a[0], a[1], a[2], a[3], b[0], b[1]);
                mma_f16(o[2 * dtp + 1], a[0], a[1], a[2], a[3], b[2], b[3]);
            }
        }
    }

    // ---- flush partial o (fp16 direct store) + row-sum partials (direct store) ----
    {
        const int rN = n0 + arow;
        __half* Og = g_Oph[z] + rN * 512 + hc;
#pragma unroll
        for (int dt = 0; dt < 8; dt++) {
            __half2 h0 = __floats2half2_rn(o[dt][0], o[dt][1]);
            __half2 h1 = __floats2half2_rn(o[dt][2], o[dt][3]);
            *(uint32_t*)&Og[dt * 8 + 2 * q] = *(uint32_t*)&h0;
            *(uint32_t*)&Og[8 * 512 + dt * 8 + 2 * q] = *(uint32_t*)&h1;
        }
    }
    rloc0 += __shfl_xor_sync(FULLM, rloc0, 1);
    rloc0 += __shfl_xor_sync(FULLM, rloc0, 2);
    rloc1 += __shfl_xor_sync(FULLM, rloc1, 1);
    rloc1 += __shfl_xor_sync(FULLM, rloc1, 2);
    if (q == 0) {
        g_sumP[z][head * Nn + n0 + arow] = rloc0;
        g_sumP[z][head * Nn + n0 + arow + 8] = rloc1;
    }
}

// ---------------------------------------------------------------------------
// Output GEMM (fp16 mma): out = ((S0+S1) * inv) @ Wo + bias. grid (4, 32, 2).
// A-staging merges two fp16 slabs in fp32 and normalizes.
// ---------------------------------------------------------------------------
__global__ __launch_bounds__(256) void outproj_f16_kernel(Ptrs in, float* out) {
    const __half *S0h, *S1h;
    const float *inv, *W, *bias;
    float* C;
    if (blockIdx.z == 0) {
        S0h = g_Oph[2]; S1h = g_Oph[3]; inv = g_csum;
        W = in.p[12]; bias = in.p[13]; C = out;
    } else {
        S0h = g_Oph[0]; S1h = g_Oph[1]; inv = g_rsum;
        W = in.p[14]; bias = in.p[15]; C = out + Nn * 256;
    }
    __shared__ __half As[128 * 72];
    __shared__ __half Ws[64 * 72];

    const int tid = threadIdx.x;
    const int lane = tid & 31, wid = tid >> 5;
    const int q = lane & 3, g = lane >> 2;
    const int row0 = blockIdx.y * 128;
    const int col0 = blockIdx.x * 64;
    const int brow = ((lane >> 3) & 1) * 8 + (lane & 7);
    const int bcoff = (lane >> 4) * 8;
    const int arow = wid * 16 + (lane & 7) + ((lane >> 3) & 1) * 8;
    const int acoff = (lane >> 4) * 8;

    float o[8][4];
#pragma unroll
    for (int nt = 0; nt < 8; nt++)
#pragma unroll
        for (int j = 0; j < 4; j++) o[nt][j] = 0.f;

    for (int k0 = 0; k0 < 512; k0 += 64) {
        const int head = k0 >> 6;
        __syncthreads();
#pragma unroll
        for (int it = 0; it < 4; it++) {
            int j = tid + it * 256;
            int rr = j >> 3, c8 = j & 7;
            int idx = (row0 + rr) * 512 + k0 + c8 * 8;
            float iv = inv[head * Nn + row0 + rr];
            uint4 u0 = *(const uint4*)&S0h[idx];
            uint4 u1 = *(const uint4*)&S1h[idx];
            const __half2* h0 = (const __half2*)&u0;
            const __half2* h1 = (const __half2*)&u1;
            uint4 uo;
            __half2* ho = (__half2*)&uo;
#pragma unroll
            for (int e = 0; e < 4; e++) {
                float2 f0 = __half22float2(h0[e]);
                float2 f1 = __half22float2(h1[e]);
                ho[e] = __floats2half2_rn((f0.x + f1.x) * iv, (f0.y + f1.y) * iv);
            }
            *(uint4*)&As[rr * 72 + c8 * 8] = uo;
        }
#pragma unroll
        for (int it = 0; it < 2; it++) {
            int j = tid + it * 256;
            int rr = j >> 3, c8 = j & 7;
            const float* src = &W[(k0 + rr) * 256 + col0 + c8 * 8];
            *(uint4*)&Ws[rr * 72 + c8 * 8] =
                pack8h(*(const float4*)src, *(const float4*)(src + 4));
        }
        __syncthreads();
#pragma unroll
        for (int kk = 0; kk < 4; kk++) {
            uint32_t a[4];
            ldm_x4(a, As + arow * 72 + kk * 16 + acoff);
#pragma unroll
            for (int dtp = 0; dtp < 4; dtp++) {
                uint32_t b[4];
                ldm_x4_trans(b, Ws + (kk * 16 + brow) * 72 + dtp * 16 + bcoff);
                mma_f16(o[2 * dtp],     a[0], a[1], a[2], a[3], b[0], b[1]);
                mma_f16(o[2 * dtp + 1], a[0], a[1], a[2], a[3], b[2], b[3]);
            }
        }
    }

    const int r = row0 + wid * 16 + g;
#pragma unroll
    for (int nt = 0; nt < 8; nt++) {
        int c = col0 + nt * 8 + 2 * q;
        float b0 = bias[c], b1 = bias[c + 1];
        *(float2*)&C[r * 256 + c] = make_float2(o[nt][0] + b0, o[nt][1] + b1);
        *(float2*)&C[(r + 8) * 256 + c] = make_float2(o[nt][2] + b0, o[nt][3] + b1);
    }
}

extern "C" void kernel_launch(void* const* d_in, const int* in_sizes, int n_in,
                              void* d_out, int out_size) {
    Ptrs ptrs;
    for (int i = 0; i < 16; i++) ptrs.p[i] = (const float*)d_in[i];
    float* out = (float*)d_out;

    const int fused_smem = (9216 + 8 * 4608) * 2;   // 90 KB
    cudaFuncSetAttribute(fused_dir_kernel, cudaFuncAttributeMaxDynamicSharedMemorySize,
                         fused_smem);

    {
        dim3 grid(512 / 64, Nn / 128, 4);
        proj_f16_kernel<<<grid, 256>>>(ptrs);
    }
    {
        dim3 grid(Nn / 128, NHEADS, 4);
        fused_dir_kernel<<<grid, 256, fused_smem>>>();
    }
    recip_kernel<<<128, 256>>>();
    {
        dim3 grid(256 / 64, Nn / 128, 2);
        outproj_f16_kernel<<<grid, 256>>>(ptrs, out);
    }
}